// round 6
// baseline (speedup 1.0000x reference)
#include <cuda_runtime.h>

// BoundaryBCELoss: 5x clamped plus-dilation of two masks + BCE vs target, mean-reduced.
// Round 6: revert to round-4 shape (48x48 tile, 8 warps x 7-8 rows, NATURAL regs ~80,
// no launch-bounds cap -- round 5's forced 64-reg cap caused spills: L2 10.8->41.4%).
// Add: (a) sticky saturation skip -- dilation is monotone+clamped, so if every cell a
// warp owns plus its halo rows is exactly 1.0f, the iteration output is bitwise equal
// to the input (each 5-neighborhood sums >= 3 -> min(.,1)=1) and the warp skips the
// compute; (b) interior-block specialization of the per-conv re-zeroing.

#define W_IMG 384
#define H_IMG 384
#define N_IMG 64
#define TILE 48
#define HALO_Y 5
#define HALO_X 6            // even => column pairs stay 8B-aligned in gmem
#define LDIM_Y 58           // TILE + 2*HALO_Y
#define LDIM_X 60           // TILE + 2*HALO_X
#define NP 30               // column pairs (LDIM_X / 2)
#define NW 8                // warps per CTA
#define NTHREADS 256
#define ITERS 5
#define RMAX 8              // max rows per warp band (warps 0,1: 8 rows; 2..7: 7)

typedef unsigned long long u64;
#define ONE2 0x3F8000003F800000ULL

#define ADD_F32X2(o, a, b) \
    asm("add.rn.f32x2 %0, %1, %2;" : "=l"(o) : "l"(a), "l"(b))
#define PACK2(o, lo, hi) \
    asm("mov.b64 %0, {%1, %2};" : "=l"(o) : "f"(lo), "f"(hi))
#define UNPACK2(lo, hi, in) \
    asm("mov.b64 {%0, %1}, %2;" : "=f"(lo), "=f"(hi) : "l"(in))

__global__ void zero_out_kernel(float* out) { *out = 0.0f; }

__global__ __launch_bounds__(NTHREADS) void boundary_bce_fused_kernel(
    const float* __restrict__ hand,
    const float* __restrict__ obj,
    const float* __restrict__ target,
    float* __restrict__ out)
{
    // Boundary-row exchange: [parity][top/bot][warp][pair] -> {a,b} (16B)
    __shared__ __align__(16) u64 xbuf[2][2][NW][NP][2];
    __shared__ float red[NW];

    const int n   = blockIdx.z;
    const int y0  = blockIdx.y * TILE - HALO_Y;
    const int x0  = blockIdx.x * TILE - HALO_X;          // even
    const int tid = threadIdx.x;
    const int w   = tid >> 5;
    const int pl  = tid & 31;

    // Row bands over 58 rows: warps 0,1 -> 8 rows; warps 2..7 -> 7 rows.
    const int r_lo = 7 * w + (w < 2 ? w : 2);
    const int R    = (w < 2) ? 8 : 7;

    const int  gx       = x0 + 2 * pl;                    // pair {gx, gx+1} fully in or out
    const bool lane_act = (pl < NP);
    const bool col_in   = lane_act && ((unsigned)gx < W_IMG);
    const bool interior = (x0 >= 0) && (y0 >= 0) &&
                          (x0 + LDIM_X <= W_IMG) && (y0 + LDIM_Y <= H_IMG);

    const size_t img = (size_t)n * H_IMG * W_IMG;
    const float* hb = hand + img;
    const float* ob = obj + img;

    // ---- Stage band rows straight into registers (coalesced LDG.64 x2) ----
    u64 ra[RMAX], rb[RMAX];
    #pragma unroll
    for (int i = 0; i < RMAX; i++) { ra[i] = 0; rb[i] = 0; }

    #pragma unroll
    for (int i = 0; i < RMAX; i++) {
        if (i < R) {
            const int gy = y0 + r_lo + i;
            if (col_in && (unsigned)gy < H_IMG) {
                const float2 hh = *(const float2*)(hb + gy * W_IMG + gx);
                const float2 oo = *(const float2*)(ob + gy * W_IMG + gx);
                PACK2(ra[i], hh.x, oo.x);   // col 2pl   : {h, o}
                PACK2(rb[i], hh.y, oo.y);   // col 2pl+1 : {h, o}
            }
        }
    }

    // ---- 5 dilation iterations ----
    bool skip = false;
    #pragma unroll 1
    for (int k = 0; k < ITERS; k++) {
        const int p = k & 1;

        if (lane_act) {
            // publish my (old) top and bottom rows for neighbor warps
            const int bi = R - 1;
            *(ulonglong2*)&xbuf[p][0][w][pl][0] = make_ulonglong2(ra[0], rb[0]);
            *(ulonglong2*)&xbuf[p][1][w][pl][0] = make_ulonglong2(ra[bi], rb[bi]);
        }
        __syncthreads();

        u64 pa = 0, pb = 0, na = 0, nb = 0;
        if (lane_act && w > 0) {
            ulonglong2 v = *(ulonglong2*)&xbuf[p][1][w - 1][pl][0];
            pa = v.x; pb = v.y;
        }
        if (lane_act && w < NW - 1) {
            ulonglong2 v = *(ulonglong2*)&xbuf[p][0][w + 1][pl][0];
            na = v.x; nb = v.y;
        }

        if (!skip) {
            // Saturation check: if every cell I own + received halo rows == 1.0f
            // exactly, this iteration (and all later ones) is a bitwise no-op.
            bool ok = true;
            #pragma unroll
            for (int i = 0; i < RMAX; i++)
                if (i < R) ok = ok && (ra[i] == ONE2) && (rb[i] == ONE2);
            if (w > 0)      ok = ok && (pa == ONE2) && (pb == ONE2);
            if (w < NW - 1) ok = ok && (na == ONE2) && (nb == ONE2);
            ok = ok || !lane_act;            // idle lanes don't veto
            skip = __all_sync(0xffffffffu, ok);
        }

        if (!skip) {
            #pragma unroll
            for (int i = 0; i < RMAX; i++) {
                if (i < R) {
                    const u64 ca = ra[i], cb = rb[i];
                    u64 xa = na, xb = nb;
                    if (i + 1 < RMAX) {
                        if (i + 1 < R) { xa = ra[i + 1]; xb = rb[i + 1]; }
                    }
                    const u64 lf = __shfl_up_sync(0xffffffffu, cb, 1);   // col 2pl-1
                    const u64 rt = __shfl_down_sync(0xffffffffu, ca, 1); // col 2pl+2

                    // out(2pl)   = lf + ca + cb + up_a + dn_a
                    // out(2pl+1) = ca + cb + rt + up_b + dn_b  (t = ca+cb shared)
                    u64 t, s0, s1;
                    ADD_F32X2(t, ca, cb);
                    ADD_F32X2(s0, t, lf);
                    ADD_F32X2(s0, s0, pa);
                    ADD_F32X2(s0, s0, xa);
                    ADD_F32X2(s1, t, rt);
                    ADD_F32X2(s1, s1, pb);
                    ADD_F32X2(s1, s1, xb);

                    float a0, a1, b0, b1;
                    UNPACK2(a0, a1, s0);
                    UNPACK2(b0, b1, s1);
                    a0 = fminf(a0, 1.0f); a1 = fminf(a1, 1.0f);
                    b0 = fminf(b0, 1.0f); b1 = fminf(b1, 1.0f);

                    if (!interior) {
                        // Re-zero out-of-image cells: reference zero-pads EVERY conv.
                        const bool rin = (unsigned)(y0 + r_lo + i) < H_IMG;
                        const bool in  = rin && col_in;
                        a0 = in ? a0 : 0.0f;  a1 = in ? a1 : 0.0f;
                        b0 = in ? b0 : 0.0f;  b1 = in ? b1 : 0.0f;
                    }

                    pa = ca; pb = cb;            // old row becomes "up" for next row
                    PACK2(ra[i], a0, a1);
                    PACK2(rb[i], b0, b1);
                }
            }
        }
        // one sync per iter is safe: next iteration stores to the other parity slot
    }

    // ---- BCE straight from registers ----
    // inner cols: local [6,54) <=> lanes 3..26 (full pairs); inner rows: local [5,53)
    float lsum = 0.0f;
    if (pl >= 3 && pl <= 26) {
        const float* tb = target + img;
        #pragma unroll
        for (int i = 0; i < RMAX; i++) {
            if (i < R) {
                const int rl = r_lo + i;
                if (rl >= HALO_Y && rl < HALO_Y + TILE) {
                    const int gy = y0 + rl;
                    const float2 t2 = *(const float2*)(tb + gy * W_IMG + gx);
                    float h0, o0, h1, o1;
                    UNPACK2(h0, o0, ra[i]);
                    UNPACK2(h1, o1, rb[i]);
                    const float p0 = h0 * o0;
                    const float p1 = h1 * o1;
                    float c0, c1;
                    if (p0 >= 1.0f) c0 = -100.0f * (1.0f - t2.x);
                    else {
                        float lp  = fmaxf(logf(p0), -100.0f);
                        float l1p = fmaxf(logf(1.0f - p0), -100.0f);
                        c0 = t2.x * lp + (1.0f - t2.x) * l1p;
                    }
                    if (p1 >= 1.0f) c1 = -100.0f * (1.0f - t2.y);
                    else {
                        float lp  = fmaxf(logf(p1), -100.0f);
                        float l1p = fmaxf(logf(1.0f - p1), -100.0f);
                        c1 = t2.y * lp + (1.0f - t2.y) * l1p;
                    }
                    lsum += c0 + c1;
                }
            }
        }
    }

    // ---- Reduction ----
    #pragma unroll
    for (int off = 16; off > 0; off >>= 1)
        lsum += __shfl_down_sync(0xffffffffu, lsum, off);

    if (pl == 0) red[w] = lsum;
    __syncthreads();

    if (tid < NW) {
        float v = red[tid];
        #pragma unroll
        for (int off = NW / 2; off > 0; off >>= 1)
            v += __shfl_down_sync((1u << NW) - 1u, v, off);
        if (tid == 0) {
            const float inv_total = 1.0f / ((float)N_IMG * H_IMG * W_IMG);
            atomicAdd(out, -v * inv_total);
        }
    }
}

extern "C" void kernel_launch(void* const* d_in, const int* in_sizes, int n_in,
                              void* d_out, int out_size)
{
    const float* hand   = (const float*)d_in[0];
    const float* obj    = (const float*)d_in[1];
    const float* target = (const float*)d_in[2];
    float* out = (float*)d_out;

    zero_out_kernel<<<1, 1>>>(out);

    dim3 grid(W_IMG / TILE, H_IMG / TILE, N_IMG);   // 8 x 8 x 64 = 4096 blocks
    boundary_bce_fused_kernel<<<grid, NTHREADS>>>(hand, obj, target, out);
}

// round 7
// speedup vs baseline: 1.2887x; 1.2887x over previous
#include <cuda_runtime.h>

// BoundaryBCELoss: 5x clamped plus-dilation of two masks + BCE vs target, mean-reduced.
// Round 7: fix R6's regression root cause -- ra[bi] with runtime bi dynamically indexed
// a register array, demoting it to LOCAL memory (L2 10.8->33.8%, +30us). Publish via
// constant-index select instead. Keeps: register-resident 48x48 tile (8 warps x 7-8
// rows, u64-packed {hand,object}), shfl horizontal neighbors, tiny SMEM row exchange,
// sticky warp-level saturation skip (all-ones => iteration is bitwise identity),
// interior-block specialization of per-conv re-zeroing.

#define W_IMG 384
#define H_IMG 384
#define N_IMG 64
#define TILE 48
#define HALO_Y 5
#define HALO_X 6            // even => column pairs stay 8B-aligned in gmem
#define LDIM_Y 58           // TILE + 2*HALO_Y
#define LDIM_X 60           // TILE + 2*HALO_X
#define NP 30               // column pairs (LDIM_X / 2)
#define NW 8                // warps per CTA
#define NTHREADS 256
#define ITERS 5
#define RMAX 8              // max rows per warp band (warps 0,1: 8 rows; 2..7: 7)

typedef unsigned long long u64;
#define ONE2 0x3F8000003F800000ULL

#define ADD_F32X2(o, a, b) \
    asm("add.rn.f32x2 %0, %1, %2;" : "=l"(o) : "l"(a), "l"(b))
#define PACK2(o, lo, hi) \
    asm("mov.b64 %0, {%1, %2};" : "=l"(o) : "f"(lo), "f"(hi))
#define UNPACK2(lo, hi, in) \
    asm("mov.b64 {%0, %1}, %2;" : "=f"(lo), "=f"(hi) : "l"(in))

__global__ void zero_out_kernel(float* out) { *out = 0.0f; }

__global__ __launch_bounds__(NTHREADS) void boundary_bce_fused_kernel(
    const float* __restrict__ hand,
    const float* __restrict__ obj,
    const float* __restrict__ target,
    float* __restrict__ out)
{
    // Boundary-row exchange: [parity][top/bot][warp][pair] -> {a,b} (16B)
    __shared__ __align__(16) u64 xbuf[2][2][NW][NP][2];
    __shared__ float red[NW];

    const int n   = blockIdx.z;
    const int y0  = blockIdx.y * TILE - HALO_Y;
    const int x0  = blockIdx.x * TILE - HALO_X;          // even
    const int tid = threadIdx.x;
    const int w   = tid >> 5;
    const int pl  = tid & 31;

    // Row bands over 58 rows: warps 0,1 -> 8 rows; warps 2..7 -> 7 rows.
    const int r_lo = 7 * w + (w < 2 ? w : 2);
    const int R    = (w < 2) ? 8 : 7;

    const int  gx       = x0 + 2 * pl;                    // pair {gx, gx+1} fully in or out
    const bool lane_act = (pl < NP);
    const bool col_in   = lane_act && ((unsigned)gx < W_IMG);
    const bool interior = (x0 >= 0) && (y0 >= 0) &&
                          (x0 + LDIM_X <= W_IMG) && (y0 + LDIM_Y <= H_IMG);

    const size_t img = (size_t)n * H_IMG * W_IMG;
    const float* hb = hand + img;
    const float* ob = obj + img;

    // ---- Stage band rows straight into registers (coalesced LDG.64 x2) ----
    u64 ra[RMAX], rb[RMAX];
    #pragma unroll
    for (int i = 0; i < RMAX; i++) { ra[i] = 0; rb[i] = 0; }

    #pragma unroll
    for (int i = 0; i < RMAX; i++) {
        if (i < R) {
            const int gy = y0 + r_lo + i;
            if (col_in && (unsigned)gy < H_IMG) {
                const float2 hh = *(const float2*)(hb + gy * W_IMG + gx);
                const float2 oo = *(const float2*)(ob + gy * W_IMG + gx);
                PACK2(ra[i], hh.x, oo.x);   // col 2pl   : {h, o}
                PACK2(rb[i], hh.y, oo.y);   // col 2pl+1 : {h, o}
            }
        }
    }

    // ---- 5 dilation iterations ----
    bool skip = false;
    #pragma unroll 1
    for (int k = 0; k < ITERS; k++) {
        const int p = k & 1;

        if (lane_act) {
            // publish my (old) top and bottom rows for neighbor warps
            // CONSTANT-index select (ra[R-1] would demote the array to local mem!)
            const u64 ba = (R == 8) ? ra[7] : ra[6];
            const u64 bb = (R == 8) ? rb[7] : rb[6];
            *(ulonglong2*)&xbuf[p][0][w][pl][0] = make_ulonglong2(ra[0], rb[0]);
            *(ulonglong2*)&xbuf[p][1][w][pl][0] = make_ulonglong2(ba, bb);
        }
        __syncthreads();

        u64 pa = 0, pb = 0, na = 0, nb = 0;
        if (lane_act && w > 0) {
            ulonglong2 v = *(ulonglong2*)&xbuf[p][1][w - 1][pl][0];
            pa = v.x; pb = v.y;
        }
        if (lane_act && w < NW - 1) {
            ulonglong2 v = *(ulonglong2*)&xbuf[p][0][w + 1][pl][0];
            na = v.x; nb = v.y;
        }

        if (!skip) {
            // Saturation check: if every cell I own + received halo rows == 1.0f
            // exactly, this iteration (and all later ones) is a bitwise no-op
            // (every 5-neighborhood sums >= 3 -> min(.,1) = 1). Sticky.
            bool ok = true;
            #pragma unroll
            for (int i = 0; i < RMAX; i++)
                if (i < R) ok = ok && (ra[i] == ONE2) && (rb[i] == ONE2);
            if (w > 0)      ok = ok && (pa == ONE2) && (pb == ONE2);
            if (w < NW - 1) ok = ok && (na == ONE2) && (nb == ONE2);
            ok = ok || !lane_act;            // idle lanes don't veto
            skip = __all_sync(0xffffffffu, ok);
        }

        if (!skip) {
            #pragma unroll
            for (int i = 0; i < RMAX; i++) {
                if (i < R) {
                    const u64 ca = ra[i], cb = rb[i];
                    u64 xa = na, xb = nb;
                    if (i + 1 < RMAX) {
                        if (i + 1 < R) { xa = ra[i + 1]; xb = rb[i + 1]; }
                    }
                    const u64 lf = __shfl_up_sync(0xffffffffu, cb, 1);   // col 2pl-1
                    const u64 rt = __shfl_down_sync(0xffffffffu, ca, 1); // col 2pl+2

                    // out(2pl)   = lf + ca + cb + up_a + dn_a
                    // out(2pl+1) = ca + cb + rt + up_b + dn_b  (t = ca+cb shared)
                    u64 t, s0, s1;
                    ADD_F32X2(t, ca, cb);
                    ADD_F32X2(s0, t, lf);
                    ADD_F32X2(s0, s0, pa);
                    ADD_F32X2(s0, s0, xa);
                    ADD_F32X2(s1, t, rt);
                    ADD_F32X2(s1, s1, pb);
                    ADD_F32X2(s1, s1, xb);

                    float a0, a1, b0, b1;
                    UNPACK2(a0, a1, s0);
                    UNPACK2(b0, b1, s1);
                    a0 = fminf(a0, 1.0f); a1 = fminf(a1, 1.0f);
                    b0 = fminf(b0, 1.0f); b1 = fminf(b1, 1.0f);

                    if (!interior) {
                        // Re-zero out-of-image cells: reference zero-pads EVERY conv.
                        const bool rin = (unsigned)(y0 + r_lo + i) < H_IMG;
                        const bool in  = rin && col_in;
                        a0 = in ? a0 : 0.0f;  a1 = in ? a1 : 0.0f;
                        b0 = in ? b0 : 0.0f;  b1 = in ? b1 : 0.0f;
                    }

                    pa = ca; pb = cb;            // old row becomes "up" for next row
                    PACK2(ra[i], a0, a1);
                    PACK2(rb[i], b0, b1);
                }
            }
        }
        // one sync per iter is safe: next iteration stores to the other parity slot
    }

    // ---- BCE straight from registers ----
    // inner cols: local [6,54) <=> lanes 3..26 (full pairs); inner rows: local [5,53)
    float lsum = 0.0f;
    if (pl >= 3 && pl <= 26) {
        const float* tb = target + img;
        #pragma unroll
        for (int i = 0; i < RMAX; i++) {
            if (i < R) {
                const int rl = r_lo + i;
                if (rl >= HALO_Y && rl < HALO_Y + TILE) {
                    const int gy = y0 + rl;
                    const float2 t2 = *(const float2*)(tb + gy * W_IMG + gx);
                    float h0, o0, h1, o1;
                    UNPACK2(h0, o0, ra[i]);
                    UNPACK2(h1, o1, rb[i]);
                    const float p0 = h0 * o0;
                    const float p1 = h1 * o1;
                    float c0, c1;
                    if (p0 >= 1.0f) c0 = -100.0f * (1.0f - t2.x);
                    else {
                        float lp  = fmaxf(logf(p0), -100.0f);
                        float l1p = fmaxf(logf(1.0f - p0), -100.0f);
                        c0 = t2.x * lp + (1.0f - t2.x) * l1p;
                    }
                    if (p1 >= 1.0f) c1 = -100.0f * (1.0f - t2.y);
                    else {
                        float lp  = fmaxf(logf(p1), -100.0f);
                        float l1p = fmaxf(logf(1.0f - p1), -100.0f);
                        c1 = t2.y * lp + (1.0f - t2.y) * l1p;
                    }
                    lsum += c0 + c1;
                }
            }
        }
    }

    // ---- Reduction ----
    #pragma unroll
    for (int off = 16; off > 0; off >>= 1)
        lsum += __shfl_down_sync(0xffffffffu, lsum, off);

    if (pl == 0) red[w] = lsum;
    __syncthreads();

    if (tid < NW) {
        float v = red[tid];
        #pragma unroll
        for (int off = NW / 2; off > 0; off >>= 1)
            v += __shfl_down_sync((1u << NW) - 1u, v, off);
        if (tid == 0) {
            const float inv_total = 1.0f / ((float)N_IMG * H_IMG * W_IMG);
            atomicAdd(out, -v * inv_total);
        }
    }
}

extern "C" void kernel_launch(void* const* d_in, const int* in_sizes, int n_in,
                              void* d_out, int out_size)
{
    const float* hand   = (const float*)d_in[0];
    const float* obj    = (const float*)d_in[1];
    const float* target = (const float*)d_in[2];
    float* out = (float*)d_out;

    zero_out_kernel<<<1, 1>>>(out);

    dim3 grid(W_IMG / TILE, H_IMG / TILE, N_IMG);   // 8 x 8 x 64 = 4096 blocks
    boundary_bce_fused_kernel<<<grid, NTHREADS>>>(hand, obj, target, out);
}

// round 8
// speedup vs baseline: 1.9184x; 1.4886x over previous
#include <cuda_runtime.h>

// BoundaryBCELoss: 5x clamped plus-dilation of two masks + BCE vs target, mean-reduced.
// Round 8: R7's skip NEVER fired -- the stale outer ring (never updated by the
// shrinking-region loop) holds raw h0 uniforms (<1), so lane0/warp0 always vetoed.
// New certificate: after iteration 2 the updated region is [2, LDIM-2); if every
// IN-IMAGE cell there is bitwise 1.0f (out-of-image cells exempt: they stay 0 and any
// in-image cell has itself in its neighborhood -> sum>=1 -> stays 1), iterations 3-5
// are bitwise identities and computed h2 on the inner tile == true h5. One check after
// iter 2 + __syncthreads_and -> block-wide loop break (skips publish/sync/compute of
// iters 3-5 for ALL blocks, border included). Fallback path = keep iterating (correct
// for any input). Keeps R4/R7 structure: register-resident 48x48 tile, 8 warps x 7-8
// rows, u64-packed {hand,object}, shfl horizontal, tiny SMEM row exchange.

#define W_IMG 384
#define H_IMG 384
#define N_IMG 64
#define TILE 48
#define HALO_Y 5
#define HALO_X 6            // even => column pairs stay 8B-aligned in gmem
#define LDIM_Y 58           // TILE + 2*HALO_Y
#define LDIM_X 60           // TILE + 2*HALO_X
#define NP 30               // column pairs (LDIM_X / 2)
#define NW 8                // warps per CTA
#define NTHREADS 256
#define ITERS 5
#define RMAX 8              // max rows per warp band (warps 0,1: 8 rows; 2..7: 7)

typedef unsigned long long u64;
#define ONE2 0x3F8000003F800000ULL

#define ADD_F32X2(o, a, b) \
    asm("add.rn.f32x2 %0, %1, %2;" : "=l"(o) : "l"(a), "l"(b))
#define PACK2(o, lo, hi) \
    asm("mov.b64 %0, {%1, %2};" : "=l"(o) : "f"(lo), "f"(hi))
#define UNPACK2(lo, hi, in) \
    asm("mov.b64 {%0, %1}, %2;" : "=f"(lo), "=f"(hi) : "l"(in))

__global__ void zero_out_kernel(float* out) { *out = 0.0f; }

__global__ __launch_bounds__(NTHREADS) void boundary_bce_fused_kernel(
    const float* __restrict__ hand,
    const float* __restrict__ obj,
    const float* __restrict__ target,
    float* __restrict__ out)
{
    // Boundary-row exchange: [parity][top/bot][warp][pair] -> {a,b} (16B)
    __shared__ __align__(16) u64 xbuf[2][2][NW][NP][2];
    __shared__ float red[NW];

    const int n   = blockIdx.z;
    const int y0  = blockIdx.y * TILE - HALO_Y;
    const int x0  = blockIdx.x * TILE - HALO_X;          // even
    const int tid = threadIdx.x;
    const int w   = tid >> 5;
    const int pl  = tid & 31;

    // Row bands over 58 rows: warps 0,1 -> 8 rows; warps 2..7 -> 7 rows.
    const int r_lo = 7 * w + (w < 2 ? w : 2);
    const int R    = (w < 2) ? 8 : 7;

    const int  gx       = x0 + 2 * pl;                    // pair {gx, gx+1} fully in or out
    const bool lane_act = (pl < NP);
    const bool col_in   = lane_act && ((unsigned)gx < W_IMG);
    const bool interior = (x0 >= 0) && (y0 >= 0) &&
                          (x0 + LDIM_X <= W_IMG) && (y0 + LDIM_Y <= H_IMG);

    const size_t img = (size_t)n * H_IMG * W_IMG;
    const float* hb = hand + img;
    const float* ob = obj + img;

    // ---- Stage band rows straight into registers (coalesced LDG.64 x2) ----
    u64 ra[RMAX], rb[RMAX];
    #pragma unroll
    for (int i = 0; i < RMAX; i++) { ra[i] = 0; rb[i] = 0; }

    #pragma unroll
    for (int i = 0; i < RMAX; i++) {
        if (i < R) {
            const int gy = y0 + r_lo + i;
            if (col_in && (unsigned)gy < H_IMG) {
                const float2 hh = *(const float2*)(hb + gy * W_IMG + gx);
                const float2 oo = *(const float2*)(ob + gy * W_IMG + gx);
                PACK2(ra[i], hh.x, oo.x);   // col 2pl   : {h, o}
                PACK2(rb[i], hh.y, oo.y);   // col 2pl+1 : {h, o}
            }
        }
    }

    // ---- Dilation iterations (block-wide early exit after iter 2) ----
    #pragma unroll 1
    for (int k = 0; k < ITERS; k++) {
        const int p = k & 1;

        if (lane_act) {
            // publish my (old) top and bottom rows for neighbor warps
            // CONSTANT-index select (ra[R-1] would demote the array to local mem!)
            const u64 ba = (R == 8) ? ra[7] : ra[6];
            const u64 bb = (R == 8) ? rb[7] : rb[6];
            *(ulonglong2*)&xbuf[p][0][w][pl][0] = make_ulonglong2(ra[0], rb[0]);
            *(ulonglong2*)&xbuf[p][1][w][pl][0] = make_ulonglong2(ba, bb);
        }
        __syncthreads();

        u64 pa = 0, pb = 0, na = 0, nb = 0;
        if (lane_act && w > 0) {
            ulonglong2 v = *(ulonglong2*)&xbuf[p][1][w - 1][pl][0];
            pa = v.x; pb = v.y;
        }
        if (lane_act && w < NW - 1) {
            ulonglong2 v = *(ulonglong2*)&xbuf[p][0][w + 1][pl][0];
            na = v.x; nb = v.y;
        }

        #pragma unroll
        for (int i = 0; i < RMAX; i++) {
            if (i < R) {
                const u64 ca = ra[i], cb = rb[i];
                u64 xa = na, xb = nb;
                if (i + 1 < RMAX) {
                    if (i + 1 < R) { xa = ra[i + 1]; xb = rb[i + 1]; }
                }
                const u64 lf = __shfl_up_sync(0xffffffffu, cb, 1);   // col 2pl-1
                const u64 rt = __shfl_down_sync(0xffffffffu, ca, 1); // col 2pl+2

                // out(2pl)   = lf + ca + cb + up_a + dn_a
                // out(2pl+1) = ca + cb + rt + up_b + dn_b  (t = ca+cb shared)
                u64 t, s0, s1;
                ADD_F32X2(t, ca, cb);
                ADD_F32X2(s0, t, lf);
                ADD_F32X2(s0, s0, pa);
                ADD_F32X2(s0, s0, xa);
                ADD_F32X2(s1, t, rt);
                ADD_F32X2(s1, s1, pb);
                ADD_F32X2(s1, s1, xb);

                float a0, a1, b0, b1;
                UNPACK2(a0, a1, s0);
                UNPACK2(b0, b1, s1);
                a0 = fminf(a0, 1.0f); a1 = fminf(a1, 1.0f);
                b0 = fminf(b0, 1.0f); b1 = fminf(b1, 1.0f);

                if (!interior) {
                    // Re-zero out-of-image cells: reference zero-pads EVERY conv.
                    const bool rin = (unsigned)(y0 + r_lo + i) < H_IMG;
                    const bool in  = rin && col_in;
                    a0 = in ? a0 : 0.0f;  a1 = in ? a1 : 0.0f;
                    b0 = in ? b0 : 0.0f;  b1 = in ? b1 : 0.0f;
                }

                pa = ca; pb = cb;            // old row becomes "up" for next row
                PACK2(ra[i], a0, a1);
                PACK2(rb[i], b0, b1);
            }
        }

        if (k == 1) {
            // Certificate: updated region after iter 2 is [2, LDIM-2)^2. If every
            // IN-IMAGE cell there is bitwise 1.0f, iterations 3-5 are identities
            // (in-image cells keep sum >= own value = 1; out-of-image stay 0) and
            // the inner-tile values already equal the true h5/o5.
            bool ok = true;
            if (col_in && pl >= 1 && pl <= 28) {     // cols 2..57 = [2, LDIM_X-2)
                #pragma unroll
                for (int i = 0; i < RMAX; i++) {
                    if (i < R) {
                        const int rl = r_lo + i;
                        if (rl >= 2 && rl < LDIM_Y - 2) {
                            if ((unsigned)(y0 + rl) < H_IMG)   // in-image rows only
                                ok = ok && (ra[i] == ONE2) && (rb[i] == ONE2);
                        }
                    }
                }
            }
            if (__syncthreads_and(ok)) break;   // block-uniform exit
        }
        // one sync per iter is safe: next iteration stores to the other parity slot
    }

    // ---- BCE straight from registers ----
    // inner cols: local [6,54) <=> lanes 3..26 (full pairs); inner rows: local [5,53)
    float lsum = 0.0f;
    if (pl >= 3 && pl <= 26) {
        const float* tb = target + img;
        #pragma unroll
        for (int i = 0; i < RMAX; i++) {
            if (i < R) {
                const int rl = r_lo + i;
                if (rl >= HALO_Y && rl < HALO_Y + TILE) {
                    const int gy = y0 + rl;
                    const float2 t2 = *(const float2*)(tb + gy * W_IMG + gx);
                    float h0, o0, h1, o1;
                    UNPACK2(h0, o0, ra[i]);
                    UNPACK2(h1, o1, rb[i]);
                    const float p0 = h0 * o0;
                    const float p1 = h1 * o1;
                    float c0, c1;
                    if (p0 >= 1.0f) c0 = -100.0f * (1.0f - t2.x);
                    else {
                        float lp  = fmaxf(logf(p0), -100.0f);
                        float l1p = fmaxf(logf(1.0f - p0), -100.0f);
                        c0 = t2.x * lp + (1.0f - t2.x) * l1p;
                    }
                    if (p1 >= 1.0f) c1 = -100.0f * (1.0f - t2.y);
                    else {
                        float lp  = fmaxf(logf(p1), -100.0f);
                        float l1p = fmaxf(logf(1.0f - p1), -100.0f);
                        c1 = t2.y * lp + (1.0f - t2.y) * l1p;
                    }
                    lsum += c0 + c1;
                }
            }
        }
    }

    // ---- Reduction ----
    #pragma unroll
    for (int off = 16; off > 0; off >>= 1)
        lsum += __shfl_down_sync(0xffffffffu, lsum, off);

    if (pl == 0) red[w] = lsum;
    __syncthreads();

    if (tid < NW) {
        float v = red[tid];
        #pragma unroll
        for (int off = NW / 2; off > 0; off >>= 1)
            v += __shfl_down_sync((1u << NW) - 1u, v, off);
        if (tid == 0) {
            const float inv_total = 1.0f / ((float)N_IMG * H_IMG * W_IMG);
            atomicAdd(out, -v * inv_total);
        }
    }
}

extern "C" void kernel_launch(void* const* d_in, const int* in_sizes, int n_in,
                              void* d_out, int out_size)
{
    const float* hand   = (const float*)d_in[0];
    const float* obj    = (const float*)d_in[1];
    const float* target = (const float*)d_in[2];
    float* out = (float*)d_out;

    zero_out_kernel<<<1, 1>>>(out);

    dim3 grid(W_IMG / TILE, H_IMG / TILE, N_IMG);   // 8 x 8 x 64 = 4096 blocks
    boundary_bce_fused_kernel<<<grid, NTHREADS>>>(hand, obj, target, out);
}

// round 9
// speedup vs baseline: 2.4843x; 1.2950x over previous
#include <cuda_runtime.h>

// BoundaryBCELoss: 5x clamped plus-dilation of two masks + BCE vs target, mean-reduced.
// Round 9: split on the R8 certificate. Kernel A: halo-2 (52x52 local, 1.17x overwork
// vs 1.51x), 2 iterations, cert = all inner-tile cells bitwise 1.0f (inner tile is
// exactly the exact-h2 region for halo-2; monotonicity makes the cert local: in-image
// cell==1 stays 1 forever) -> BCE collapses to -100*sum(1-t), no branches/MUFU; on
// fail write flag. Kernel B: R8's halo-5 full 5-iteration kernel, same grid, early
// return unless flagged (expected O(1) blocks). Deterministic: A writes every flag
// every call; launches ordered on one stream.

#define W_IMG 384
#define H_IMG 384
#define N_IMG 64
#define TILE 48
#define NBLK 4096            // 8*8*64

// ---- fast kernel (A) geometry: halo 2 ----
#define A_HALO 2
#define A_LDIM 52            // TILE + 4
#define A_NP 26              // column pairs
#define A_RMAX 7             // warps 0-3: 7 rows, warps 4-7: 6 rows

// ---- fallback kernel (B) geometry: halo 5 (x-halo 6 for 8B alignment) ----
#define B_HALO_Y 5
#define B_HALO_X 6
#define B_LDIM_Y 58
#define B_LDIM_X 60
#define B_NP 30
#define B_RMAX 8             // warps 0,1: 8 rows, warps 2-7: 7 rows

#define NW 8
#define NTHREADS 256

typedef unsigned long long u64;
#define ONE2 0x3F8000003F800000ULL

#define ADD_F32X2(o, a, b) \
    asm("add.rn.f32x2 %0, %1, %2;" : "=l"(o) : "l"(a), "l"(b))
#define PACK2(o, lo, hi) \
    asm("mov.b64 %0, {%1, %2};" : "=l"(o) : "f"(lo), "f"(hi))
#define UNPACK2(lo, hi, in) \
    asm("mov.b64 {%0, %1}, %2;" : "=f"(lo), "=f"(hi) : "l"(in))

__device__ int g_flags[NBLK];

__global__ void zero_out_kernel(float* out) { *out = 0.0f; }

// ============================ Kernel A: fast path ============================
__global__ __launch_bounds__(NTHREADS) void bce_fast_kernel(
    const float* __restrict__ hand,
    const float* __restrict__ obj,
    const float* __restrict__ target,
    float* __restrict__ out)
{
    __shared__ __align__(16) u64 xbuf[2][2][NW][A_NP][2];
    __shared__ float red[NW];

    const int n   = blockIdx.z;
    const int y0  = blockIdx.y * TILE - A_HALO;
    const int x0  = blockIdx.x * TILE - A_HALO;          // even
    const int tid = threadIdx.x;
    const int w   = tid >> 5;
    const int pl  = tid & 31;
    const int bid = (blockIdx.z * gridDim.y + blockIdx.y) * gridDim.x + blockIdx.x;

    // Row bands over 52 rows: warps 0-3 -> 7 rows; warps 4-7 -> 6 rows.
    const int r_lo = (w < 4) ? 7 * w : 6 * w + 4;
    const int R    = (w < 4) ? 7 : 6;

    const int  gx       = x0 + 2 * pl;
    const bool lane_act = (pl < A_NP);
    const bool col_in   = lane_act && ((unsigned)gx < W_IMG);
    const bool interior = (x0 >= 0) && (y0 >= 0) &&
                          (x0 + A_LDIM <= W_IMG) && (y0 + A_LDIM <= H_IMG);

    const size_t img = (size_t)n * H_IMG * W_IMG;
    const float* hb = hand + img;
    const float* ob = obj + img;

    // ---- Stage band rows into registers ----
    u64 ra[A_RMAX], rb[A_RMAX];
    #pragma unroll
    for (int i = 0; i < A_RMAX; i++) { ra[i] = 0; rb[i] = 0; }

    #pragma unroll
    for (int i = 0; i < A_RMAX; i++) {
        if (i < R) {
            const int gy = y0 + r_lo + i;
            if (col_in && (unsigned)gy < H_IMG) {
                const float2 hh = *(const float2*)(hb + gy * W_IMG + gx);
                const float2 oo = *(const float2*)(ob + gy * W_IMG + gx);
                PACK2(ra[i], hh.x, oo.x);
                PACK2(rb[i], hh.y, oo.y);
            }
        }
    }

    // ---- 2 dilation iterations (ring wrongness propagates 1 row/iter; with
    //      halo 2 the inner tile holds EXACT h2/o2 afterwards) ----
    #pragma unroll
    for (int k = 0; k < 2; k++) {
        const int p = k;

        if (lane_act) {
            const u64 ba = (R == 7) ? ra[6] : ra[5];   // constant-index select!
            const u64 bb = (R == 7) ? rb[6] : rb[5];
            *(ulonglong2*)&xbuf[p][0][w][pl][0] = make_ulonglong2(ra[0], rb[0]);
            *(ulonglong2*)&xbuf[p][1][w][pl][0] = make_ulonglong2(ba, bb);
        }
        __syncthreads();

        u64 pa = 0, pb = 0, na = 0, nb = 0;
        if (lane_act && w > 0) {
            ulonglong2 v = *(ulonglong2*)&xbuf[p][1][w - 1][pl][0];
            pa = v.x; pb = v.y;
        }
        if (lane_act && w < NW - 1) {
            ulonglong2 v = *(ulonglong2*)&xbuf[p][0][w + 1][pl][0];
            na = v.x; nb = v.y;
        }

        #pragma unroll
        for (int i = 0; i < A_RMAX; i++) {
            if (i < R) {
                const u64 ca = ra[i], cb = rb[i];
                u64 xa = na, xb = nb;
                if (i + 1 < A_RMAX) {
                    if (i + 1 < R) { xa = ra[i + 1]; xb = rb[i + 1]; }
                }
                const u64 lf = __shfl_up_sync(0xffffffffu, cb, 1);
                const u64 rt = __shfl_down_sync(0xffffffffu, ca, 1);

                u64 t, s0, s1;
                ADD_F32X2(t, ca, cb);
                ADD_F32X2(s0, t, lf);
                ADD_F32X2(s0, s0, pa);
                ADD_F32X2(s0, s0, xa);
                ADD_F32X2(s1, t, rt);
                ADD_F32X2(s1, s1, pb);
                ADD_F32X2(s1, s1, xb);

                float a0, a1, b0, b1;
                UNPACK2(a0, a1, s0);
                UNPACK2(b0, b1, s1);
                a0 = fminf(a0, 1.0f); a1 = fminf(a1, 1.0f);
                b0 = fminf(b0, 1.0f); b1 = fminf(b1, 1.0f);

                if (!interior) {
                    const bool rin = (unsigned)(y0 + r_lo + i) < H_IMG;
                    const bool in  = rin && col_in;
                    a0 = in ? a0 : 0.0f;  a1 = in ? a1 : 0.0f;
                    b0 = in ? b0 : 0.0f;  b1 = in ? b1 : 0.0f;
                }

                pa = ca; pb = cb;
                PACK2(ra[i], a0, a1);
                PACK2(rb[i], b0, b1);
            }
        }
        // one sync per iter: next iteration stores to the other parity slot
    }

    // ---- Certificate: all inner-tile cells (exact h2/o2, always in-image)
    //      bitwise {1.0f,1.0f} => true h5=o5=1 on the whole inner tile ----
    bool ok = true;
    if (pl >= 1 && pl <= 24) {                   // cols local [2,50)
        #pragma unroll
        for (int i = 0; i < A_RMAX; i++) {
            if (i < R) {
                const int rl = r_lo + i;
                if (rl >= A_HALO && rl < A_HALO + TILE)
                    ok = ok && (ra[i] == ONE2) && (rb[i] == ONE2);
            }
        }
    }
    const bool pass = __syncthreads_and(ok);

    if (tid == 0) g_flags[bid] = pass ? 0 : 1;
    if (!pass) return;                           // fallback kernel owns this block

    // ---- BCE with p==1 everywhere: contrib = -100*(1-t) ----
    float ts = 0.0f;
    int cells = 0;
    if (pl >= 1 && pl <= 24) {
        const float* tb = target + img;
        #pragma unroll
        for (int i = 0; i < A_RMAX; i++) {
            if (i < R) {
                const int rl = r_lo + i;
                if (rl >= A_HALO && rl < A_HALO + TILE) {
                    const float2 t2 = *(const float2*)(tb + (y0 + rl) * W_IMG + gx);
                    ts += t2.x + t2.y;
                    cells += 2;
                }
            }
        }
    }
    float lsum = -100.0f * ((float)cells - ts);

    #pragma unroll
    for (int off = 16; off > 0; off >>= 1)
        lsum += __shfl_down_sync(0xffffffffu, lsum, off);

    if (pl == 0) red[w] = lsum;
    __syncthreads();

    if (tid < NW) {
        float v = red[tid];
        #pragma unroll
        for (int off = NW / 2; off > 0; off >>= 1)
            v += __shfl_down_sync((1u << NW) - 1u, v, off);
        if (tid == 0) {
            const float inv_total = 1.0f / ((float)N_IMG * H_IMG * W_IMG);
            atomicAdd(out, -v * inv_total);
        }
    }
}

// ========================= Kernel B: rare fallback ==========================
__global__ __launch_bounds__(NTHREADS) void bce_fallback_kernel(
    const float* __restrict__ hand,
    const float* __restrict__ obj,
    const float* __restrict__ target,
    float* __restrict__ out)
{
    const int bid = (blockIdx.z * gridDim.y + blockIdx.y) * gridDim.x + blockIdx.x;
    if (g_flags[bid] == 0) return;               // block-uniform early exit

    __shared__ __align__(16) u64 xbuf[2][2][NW][B_NP][2];
    __shared__ float red[NW];

    const int n   = blockIdx.z;
    const int y0  = blockIdx.y * TILE - B_HALO_Y;
    const int x0  = blockIdx.x * TILE - B_HALO_X;        // even
    const int tid = threadIdx.x;
    const int w   = tid >> 5;
    const int pl  = tid & 31;

    const int r_lo = 7 * w + (w < 2 ? w : 2);
    const int R    = (w < 2) ? 8 : 7;

    const int  gx       = x0 + 2 * pl;
    const bool lane_act = (pl < B_NP);
    const bool col_in   = lane_act && ((unsigned)gx < W_IMG);
    const bool interior = (x0 >= 0) && (y0 >= 0) &&
                          (x0 + B_LDIM_X <= W_IMG) && (y0 + B_LDIM_Y <= H_IMG);

    const size_t img = (size_t)n * H_IMG * W_IMG;
    const float* hb = hand + img;
    const float* ob = obj + img;

    u64 ra[B_RMAX], rb[B_RMAX];
    #pragma unroll
    for (int i = 0; i < B_RMAX; i++) { ra[i] = 0; rb[i] = 0; }

    #pragma unroll
    for (int i = 0; i < B_RMAX; i++) {
        if (i < R) {
            const int gy = y0 + r_lo + i;
            if (col_in && (unsigned)gy < H_IMG) {
                const float2 hh = *(const float2*)(hb + gy * W_IMG + gx);
                const float2 oo = *(const float2*)(ob + gy * W_IMG + gx);
                PACK2(ra[i], hh.x, oo.x);
                PACK2(rb[i], hh.y, oo.y);
            }
        }
    }

    #pragma unroll 1
    for (int k = 0; k < 5; k++) {
        const int p = k & 1;

        if (lane_act) {
            const u64 ba = (R == 8) ? ra[7] : ra[6];     // constant-index select!
            const u64 bb = (R == 8) ? rb[7] : rb[6];
            *(ulonglong2*)&xbuf[p][0][w][pl][0] = make_ulonglong2(ra[0], rb[0]);
            *(ulonglong2*)&xbuf[p][1][w][pl][0] = make_ulonglong2(ba, bb);
        }
        __syncthreads();

        u64 pa = 0, pb = 0, na = 0, nb = 0;
        if (lane_act && w > 0) {
            ulonglong2 v = *(ulonglong2*)&xbuf[p][1][w - 1][pl][0];
            pa = v.x; pb = v.y;
        }
        if (lane_act && w < NW - 1) {
            ulonglong2 v = *(ulonglong2*)&xbuf[p][0][w + 1][pl][0];
            na = v.x; nb = v.y;
        }

        #pragma unroll
        for (int i = 0; i < B_RMAX; i++) {
            if (i < R) {
                const u64 ca = ra[i], cb = rb[i];
                u64 xa = na, xb = nb;
                if (i + 1 < B_RMAX) {
                    if (i + 1 < R) { xa = ra[i + 1]; xb = rb[i + 1]; }
                }
                const u64 lf = __shfl_up_sync(0xffffffffu, cb, 1);
                const u64 rt = __shfl_down_sync(0xffffffffu, ca, 1);

                u64 t, s0, s1;
                ADD_F32X2(t, ca, cb);
                ADD_F32X2(s0, t, lf);
                ADD_F32X2(s0, s0, pa);
                ADD_F32X2(s0, s0, xa);
                ADD_F32X2(s1, t, rt);
                ADD_F32X2(s1, s1, pb);
                ADD_F32X2(s1, s1, xb);

                float a0, a1, b0, b1;
                UNPACK2(a0, a1, s0);
                UNPACK2(b0, b1, s1);
                a0 = fminf(a0, 1.0f); a1 = fminf(a1, 1.0f);
                b0 = fminf(b0, 1.0f); b1 = fminf(b1, 1.0f);

                if (!interior) {
                    const bool rin = (unsigned)(y0 + r_lo + i) < H_IMG;
                    const bool in  = rin && col_in;
                    a0 = in ? a0 : 0.0f;  a1 = in ? a1 : 0.0f;
                    b0 = in ? b0 : 0.0f;  b1 = in ? b1 : 0.0f;
                }

                pa = ca; pb = cb;
                PACK2(ra[i], a0, a1);
                PACK2(rb[i], b0, b1);
            }
        }
    }

    // ---- Full BCE (inner cols local [6,54) <=> lanes 3..26; rows [5,53)) ----
    float lsum = 0.0f;
    if (pl >= 3 && pl <= 26) {
        const float* tb = target + img;
        #pragma unroll
        for (int i = 0; i < B_RMAX; i++) {
            if (i < R) {
                const int rl = r_lo + i;
                if (rl >= B_HALO_Y && rl < B_HALO_Y + TILE) {
                    const float2 t2 = *(const float2*)(tb + (y0 + rl) * W_IMG + gx);
                    float h0, o0, h1, o1;
                    UNPACK2(h0, o0, ra[i]);
                    UNPACK2(h1, o1, rb[i]);
                    const float p0 = h0 * o0;
                    const float p1 = h1 * o1;
                    float c0, c1;
                    if (p0 >= 1.0f) c0 = -100.0f * (1.0f - t2.x);
                    else {
                        float lp  = fmaxf(logf(p0), -100.0f);
                        float l1p = fmaxf(logf(1.0f - p0), -100.0f);
                        c0 = t2.x * lp + (1.0f - t2.x) * l1p;
                    }
                    if (p1 >= 1.0f) c1 = -100.0f * (1.0f - t2.y);
                    else {
                        float lp  = fmaxf(logf(p1), -100.0f);
                        float l1p = fmaxf(logf(1.0f - p1), -100.0f);
                        c1 = t2.y * lp + (1.0f - t2.y) * l1p;
                    }
                    lsum += c0 + c1;
                }
            }
        }
    }

    #pragma unroll
    for (int off = 16; off > 0; off >>= 1)
        lsum += __shfl_down_sync(0xffffffffu, lsum, off);

    if (pl == 0) red[w] = lsum;
    __syncthreads();

    if (tid < NW) {
        float v = red[tid];
        #pragma unroll
        for (int off = NW / 2; off > 0; off >>= 1)
            v += __shfl_down_sync((1u << NW) - 1u, v, off);
        if (tid == 0) {
            const float inv_total = 1.0f / ((float)N_IMG * H_IMG * W_IMG);
            atomicAdd(out, -v * inv_total);
        }
    }
}

extern "C" void kernel_launch(void* const* d_in, const int* in_sizes, int n_in,
                              void* d_out, int out_size)
{
    const float* hand   = (const float*)d_in[0];
    const float* obj    = (const float*)d_in[1];
    const float* target = (const float*)d_in[2];
    float* out = (float*)d_out;

    zero_out_kernel<<<1, 1>>>(out);

    dim3 grid(W_IMG / TILE, H_IMG / TILE, N_IMG);    // 8 x 8 x 64 = 4096 blocks
    bce_fast_kernel<<<grid, NTHREADS>>>(hand, obj, target, out);
    bce_fallback_kernel<<<grid, NTHREADS>>>(hand, obj, target, out);
}